// round 4
// baseline (speedup 1.0000x reference)
#include <cuda_runtime.h>

#define Bq 16
#define Sq 128
#define Dq 300
#define Oq 64
#define Eq 16
#define Tq 45
#define TP 48               // padded type count
#define ROWS_TOT 2048
#define WROW 316
#define KT 60               // K-chunk
#define CST 68              // smem col stride (floats): 272B, 16B-aligned, lane-stride 4 banks
#define NSEG_COLS 240       // 64 hi | 64 hj | 64 ht | 48 S

// __device__ scratch (allocation-free rule)
__device__ float g_ht[ROWS_TOT*Oq];
__device__ float g_E [ROWS_TOT*TP];
__device__ float g_e [TP];
__device__ float g_Vt[TP*304];     // V transposed [t][k], rowlen 304

// ---------------------------------------------------------------------------
// prep: each block computes U1/U2 (dep-type fold through W1/W2 tails) in smem,
//       then V[t][kbase..kbase+3] -> g_Vt. Block 0 also computes e[t].
//       75 blocks x 192 threads.
// ---------------------------------------------------------------------------
__global__ void __launch_bounds__(192) prep_kernel(
        const float* __restrict__ dep_table,
        const float* __restrict__ W1, const float* __restrict__ b1,
        const float* __restrict__ W2, const float* __restrict__ b2) {
    __shared__ float sU1[Oq*TP], sU2[Oq*TP];   // [o][t]
    int tid = threadIdx.x;
    int kbase = blockIdx.x * 4;

    for (int i = tid; i < Tq*Oq; i += 192) {
        int t = i / Oq, o = i - t*Oq;
        float s1 = 0.f, s2 = 0.f;
        #pragma unroll
        for (int e = 0; e < Eq; e++) {
            float de = __ldg(&dep_table[t*Eq + e]);
            s1 += __ldg(&W1[o*WROW + Dq + e]) * de;
            s2 += __ldg(&W2[o*WROW + Dq + e]) * de;
        }
        sU1[o*TP + t] = s1;
        sU2[o*TP + t] = s2;
    }
    for (int i = tid; i < Oq*3; i += 192) {      // zero pad types 45..47
        int o = i / 3, t = Tq + (i % 3);
        sU1[o*TP + t] = 0.f; sU2[o*TP + t] = 0.f;
    }
    __syncthreads();

    {
        int t = tid % TP, kk = tid / TP;         // 48 x 4
        float acc = 0.f;
        const float* w1c = W1 + kbase + kk;
        const float* w2c = W2 + kbase + kk;
        #pragma unroll 8
        for (int o = 0; o < Oq; o++)
            acc += __ldg(&w1c[o*WROW]) * sU2[o*TP + t]
                 + __ldg(&w2c[o*WROW]) * sU1[o*TP + t];
        g_Vt[t*304 + kbase + kk] = acc;          // 0 for t >= 45
    }

    if (blockIdx.x == 0 && tid < TP) {
        float e = 0.f;
        #pragma unroll 8
        for (int o = 0; o < Oq; o++) {
            float u1 = sU1[o*TP + tid], u2 = sU2[o*TP + tid];
            e += b1[o]*u2 + b2[o]*u1 + u1*u2;
        }
        g_e[tid] = e;                            // 0 for t >= 45
    }
}

// ---------------------------------------------------------------------------
// gemm: 128 blocks x 256 threads. 16 rows x 240 cols, K=300 (5 chunks of 60).
//   Thread tile: 4 rows x {hi,hj,ht,S} segment cols. Epilogue builds the
//   45-entry score table, row max, exp -> g_E; hi/hj stay in smem only.
// ---------------------------------------------------------------------------
__global__ void __launch_bounds__(256) gemm_kernel(
        const float* __restrict__ h,
        const float* __restrict__ W1, const float* __restrict__ b1,
        const float* __restrict__ W2, const float* __restrict__ b2,
        const float* __restrict__ Wg, const float* __restrict__ bg,
        const unsigned char* __restrict__ mask8) {
    extern __shared__ float sm[];
    float* sh = sm;                  // 16*300 = 4800
    float* sW = sm + 16*Dq;          // 256*68 = 17408 (cols 240..255 unused)
    float* shi = sW;                 // epilogue aliases (after last sync)
    float* shj = sW + 1024;
    float* ssv = sW + 2048;          // 16*48
    float* se  = sW + 2048 + 768;    // 48
    __shared__ int sp[5];
    __shared__ float swt[16];
    __shared__ float sc0[16], smx[16];

    int tid  = threadIdx.x;
    int row0 = blockIdx.x * 16;
    int b    = row0 >> 7;

    // ---- aspect span scan (dual bool-dtype robust) ----
    if (tid < 5) sp[tid] = (tid==0 || tid==3) ? Sq : ((tid==1 || tid==4) ? -1 : 0);
    __syncthreads();
    if (tid < 128 && mask8[(b<<7) + tid]) {
        atomicMin(&sp[0], tid); atomicMax(&sp[1], tid); atomicAdd(&sp[2], 1);
    }
    __syncthreads();
    bool valid8 = (sp[2] == 3 && sp[1] - sp[0] == 2);
    if (!valid8) {
        const int* m32 = (const int*)mask8;
        if (tid < 128 && m32[(b<<7) + tid] != 0) {
            atomicMin(&sp[3], tid); atomicMax(&sp[4], tid);
        }
    }
    __syncthreads();
    int st = valid8 ? sp[0] : sp[3];
    int en = valid8 ? sp[1] : sp[4];
    if (tid < 16) {
        int s = (row0 + tid) & 127;
        float w;
        if (s < st)      w = 1.0f - (float)(st - s) * (1.0f/128.0f);
        else if (s > en) w = 1.0f - (float)(s - en) * (1.0f/128.0f);
        else             w = 0.0f;
        swt[tid] = w;
    }
    __syncthreads();

    // ---- stage position-weighted h (16 x 300) ----
    {
        const float4* h4 = (const float4*)(h + (size_t)row0 * Dq);
        float4* sh4 = (float4*)sh;
        for (int i = tid; i < 16*75; i += 256) {
            int r = i / 75;
            float4 v = h4[i];
            float w = swt[r];
            v.x *= w; v.y *= w; v.z *= w; v.w *= w;
            sh4[i] = v;
        }
    }

    int cg = tid & 63;
    int rg = tid >> 6;
    float aI[4] = {0,0,0,0}, aJ[4] = {0,0,0,0};
    float aT[4] = {0,0,0,0}, aS[4] = {0,0,0,0};

    for (int c = 0; c < Dq/KT; c++) {
        __syncthreads();
        // stage W1|W2|Wg|V column-major [col][k], STS.128
        for (int i = tid; i < NSEG_COLS*15; i += 256) {
            int col = i / 15, q = i - col*15;
            const float* src;
            if (col < 64)       src = W1   + (size_t)col      * WROW;
            else if (col < 128) src = W2   + (size_t)(col-64) * WROW;
            else if (col < 192) src = Wg   + (size_t)(col-128)* Dq;
            else                src = g_Vt + (size_t)(col-192)* 304;
            float4 v = *(const float4*)(src + c*KT + q*4);
            *(float4*)&sW[col*CST + q*4] = v;
        }
        __syncthreads();

        const float* hp = sh + rg*4*Dq + c*KT;
        const float* wI = sW + cg*CST;
        const float* wJ = sW + (64 + cg)*CST;
        const float* wT = sW + (128 + cg)*CST;
        const float* wS = sW + (192 + cg)*CST;
        #pragma unroll 5
        for (int k4 = 0; k4 < 15; k4++) {
            float4 vI = *(const float4*)&wI[k4*4];
            float4 vJ = *(const float4*)&wJ[k4*4];
            float4 vT = *(const float4*)&wT[k4*4];
            float4 vS = *(const float4*)&wS[k4*4];
            float4 h0 = *(const float4*)(hp + 0*Dq + k4*4);
            float4 h1 = *(const float4*)(hp + 1*Dq + k4*4);
            float4 h2 = *(const float4*)(hp + 2*Dq + k4*4);
            float4 h3 = *(const float4*)(hp + 3*Dq + k4*4);
            const float* hv0 = (const float*)&h0;
            const float* hv1 = (const float*)&h1;
            const float* hv2 = (const float*)&h2;
            const float* hv3 = (const float*)&h3;
            #pragma unroll
            for (int kk = 0; kk < 4; kk++) {
                float wi = ((const float*)&vI)[kk];
                float wj = ((const float*)&vJ)[kk];
                float wt = ((const float*)&vT)[kk];
                float ws = ((const float*)&vS)[kk];
                aI[0] += hv0[kk]*wi; aJ[0] += hv0[kk]*wj; aT[0] += hv0[kk]*wt; aS[0] += hv0[kk]*ws;
                aI[1] += hv1[kk]*wi; aJ[1] += hv1[kk]*wj; aT[1] += hv1[kk]*wt; aS[1] += hv1[kk]*ws;
                aI[2] += hv2[kk]*wi; aJ[2] += hv2[kk]*wj; aT[2] += hv2[kk]*wt; aS[2] += hv2[kk]*ws;
                aI[3] += hv3[kk]*wi; aJ[3] += hv3[kk]*wj; aT[3] += hv3[kk]*wt; aS[3] += hv3[kk]*ws;
            }
        }
    }
    __syncthreads();

    // ---- epilogue (sW reused) ----
    float bi = b1[cg], bj = b2[cg], bt = bg[cg];
    #pragma unroll
    for (int j = 0; j < 4; j++) {
        int row = rg*4 + j;
        shi[row*64 + cg] = aI[j] + bi;
        shj[row*64 + cg] = aJ[j] + bj;
        g_ht[(size_t)(row0 + row)*Oq + cg] = aT[j] + bt;
    }
    if (tid < TP) se[tid] = g_e[tid];
    __syncthreads();

    if (tid < 128) {                        // c0[r] = hi[r]·hj[r]
        int r = tid >> 3, p = tid & 7;
        const float* hi = shi + r*64 + p*8;
        const float* hj = shj + r*64 + p*8;
        float s = 0.f;
        #pragma unroll
        for (int q = 0; q < 8; q++) s += hi[q]*hj[q];
        s += __shfl_down_sync(0xffffffffu, s, 4, 8);
        s += __shfl_down_sync(0xffffffffu, s, 2, 8);
        s += __shfl_down_sync(0xffffffffu, s, 1, 8);
        if (p == 0) sc0[r] = s;
    }
    __syncthreads();

    if (cg < TP) {
        float ee = se[cg];
        #pragma unroll
        for (int j = 0; j < 4; j++) {
            int row = rg*4 + j;
            ssv[row*TP + cg] = (cg < Tq) ? (aS[j] + sc0[row] + ee) : -1e30f;
        }
    }
    __syncthreads();
    if (tid < 16) {
        float m = -1e30f;
        #pragma unroll 8
        for (int t = 0; t < TP; t++) m = fmaxf(m, ssv[tid*TP + t]);
        smx[tid] = m;
    }
    __syncthreads();
    for (int i = tid; i < 16*TP; i += 256) {
        int r = i / TP, t = i - r*TP;
        float v = (t > 0 && t < Tq) ? __expf((ssv[i] - smx[r]) * 0.125f) : 0.f;
        g_E[(size_t)(row0 + r)*TP + t] = v;
    }
}

// ---------------------------------------------------------------------------
// attn: 256 blocks x 256 threads, 8 rows/block. Gather e=sE[ty], row-sum,
//       out = relu((A @ h_trans)/(sum+1e-6) + bias). One warp per row.
// ---------------------------------------------------------------------------
__global__ void __launch_bounds__(256) attn_kernel(
        const int* __restrict__ dep,
        const float* __restrict__ bias,
        float* __restrict__ out) {
    __shared__ float sE[8*TP];
    __shared__ float sht[Sq*Oq];     // 32 KB
    __shared__ float sA[8*Sq];
    __shared__ float spart[8*4];
    __shared__ float sden[8];

    int tid = threadIdx.x;
    int gr0 = blockIdx.x * 8;
    int b   = gr0 >> 7;

    for (int i = tid; i < 8*TP; i += 256) sE[i] = g_E[(size_t)gr0*TP + i];
    {
        const float4* src = (const float4*)(g_ht + (size_t)b * Sq * Oq);
        float4* dst = (float4*)sht;
        for (int i = tid; i < Sq*Oq/4; i += 256) dst[i] = src[i];
    }
    __syncthreads();

    int pos = tid & 127, rh = tid >> 7;
    int wid = tid >> 5, lane = tid & 31;
    #pragma unroll
    for (int rr = 0; rr < 4; rr++) {
        int row = rr*2 + rh;
        int ty = dep[(size_t)(gr0 + row)*Sq + pos];
        float e = sE[row*TP + ty];
        sA[row*Sq + pos] = e;
        float s = e;
        #pragma unroll
        for (int off = 16; off; off >>= 1)
            s += __shfl_xor_sync(0xffffffffu, s, off);
        if (lane == 0) spart[row*4 + (wid & 3)] = s;
    }
    __syncthreads();
    if (tid < 8)
        sden[tid] = 1.0f / (spart[tid*4] + spart[tid*4+1] +
                            spart[tid*4+2] + spart[tid*4+3] + 1e-6f);
    __syncthreads();

    int o2 = tid & 31, g = tid >> 5;            // g = row (one warp per row)
    const float* Ar = sA + g*Sq;
    float ax = 0.f, ay = 0.f;
    #pragma unroll 8
    for (int u = 0; u < Sq; u += 4) {
        float4 av = *(const float4*)&Ar[u];
        float2 h0 = *(const float2*)&sht[(u+0)*Oq + o2*2];
        float2 h1 = *(const float2*)&sht[(u+1)*Oq + o2*2];
        float2 h2 = *(const float2*)&sht[(u+2)*Oq + o2*2];
        float2 h3 = *(const float2*)&sht[(u+3)*Oq + o2*2];
        ax += av.x*h0.x + av.y*h1.x + av.z*h2.x + av.w*h3.x;
        ay += av.x*h0.y + av.y*h1.y + av.z*h2.y + av.w*h3.y;
    }
    float den = sden[g];
    float2 bb = *(const float2*)&bias[o2*2];
    float ox = fmaxf(ax*den + bb.x, 0.f);
    float oy = fmaxf(ay*den + bb.y, 0.f);
    *(float2*)&out[(size_t)(gr0 + g)*Oq + o2*2] = make_float2(ox, oy);
}

// ---------------------------------------------------------------------------
// Inputs: h, dep_table, W1, b1, W2, b2, Wg, bg, bias, dep_type_matrix, aspect_mask
// ---------------------------------------------------------------------------
extern "C" void kernel_launch(void* const* d_in, const int* in_sizes, int n_in,
                              void* d_out, int out_size) {
    const float* h         = (const float*)d_in[0];
    const float* dep_table = (const float*)d_in[1];
    const float* W1        = (const float*)d_in[2];
    const float* b1        = (const float*)d_in[3];
    const float* W2        = (const float*)d_in[4];
    const float* b2        = (const float*)d_in[5];
    const float* Wg        = (const float*)d_in[6];
    const float* bg        = (const float*)d_in[7];
    const float* bias      = (const float*)d_in[8];
    const int*   dep       = (const int*)d_in[9];
    const unsigned char* mask = (const unsigned char*)d_in[10];

    const int gemm_smem = (16*Dq + 256*CST) * (int)sizeof(float);   // 88832 B
    cudaFuncSetAttribute(gemm_kernel,
                         cudaFuncAttributeMaxDynamicSharedMemorySize, gemm_smem);

    prep_kernel<<<75, 192>>>(dep_table, W1, b1, W2, b2);
    gemm_kernel<<<ROWS_TOT/16, 256, gemm_smem>>>(h, W1, b1, W2, b2, Wg, bg, mask);
    attn_kernel<<<ROWS_TOT/8, 256>>>(dep, bias, (float*)d_out);
}

// round 7
// speedup vs baseline: 1.6946x; 1.6946x over previous
#include <cuda_runtime.h>

#define Bq 16
#define Sq 128
#define Dq 300
#define Oq 64
#define Eq 16
#define Tq 45
#define TP 48               // padded type count
#define ROWS_TOT 2048
#define WROW 316
#define KT 60               // K-chunk
#define CST 68              // smem col stride (floats): 272B, 16B-aligned, 4-bank lane stride
#define NC 112              // GEMM cols: 64 ht | 48 S  (hi/hj cancel in softmax)

// __device__ scratch (allocation-free rule)
__device__ float g_ht[ROWS_TOT*Oq];
__device__ float g_E [ROWS_TOT*TP];
__device__ float g_U1[Tq*Oq];
__device__ float g_U2[Tq*Oq];
__device__ float g_e [TP];          // zero-init covers t>=45
__device__ float g_Vt[TP*304];      // V transposed [t][k], rowlen 304

// ---------------------------------------------------------------------------
// K0a: U1/U2 = dep-type embedding folded through W1/W2 tails;
//      e[t] = b1·U2[t] + b2·U1[t] + U1[t]·U2[t].   45 blocks x 64 threads.
// ---------------------------------------------------------------------------
__global__ void u_kernel(const float* __restrict__ dep_table,
                         const float* __restrict__ W1, const float* __restrict__ b1,
                         const float* __restrict__ W2, const float* __restrict__ b2) {
    __shared__ float sdt[Eq];
    __shared__ float swp[2];
    int t = blockIdx.x, o = threadIdx.x;
    if (o < Eq) sdt[o] = dep_table[t*Eq + o];
    __syncthreads();
    float s1 = 0.f, s2 = 0.f;
    #pragma unroll
    for (int e = 0; e < Eq; e++) {
        float de = sdt[e];
        s1 += __ldg(&W1[o*WROW + Dq + e]) * de;
        s2 += __ldg(&W2[o*WROW + Dq + e]) * de;
    }
    g_U1[t*Oq + o] = s1;
    g_U2[t*Oq + o] = s2;
    float v = b1[o]*s2 + b2[o]*s1 + s1*s2;
    #pragma unroll
    for (int off = 16; off; off >>= 1) v += __shfl_xor_sync(0xffffffffu, v, off);
    if ((o & 31) == 0) swp[o >> 5] = v;
    __syncthreads();
    if (o == 0) g_e[t] = swp[0] + swp[1];
}

// ---------------------------------------------------------------------------
// K0b: V[t][k] = sum_o W1[o][k]*U2[t][o] + W2[o][k]*U1[t][o]  -> g_Vt[t][k].
//      75 blocks x 192 threads (4 k x 48 t). Reads U from global (after K0a).
// ---------------------------------------------------------------------------
__global__ void __launch_bounds__(192) v_kernel(const float* __restrict__ W1,
                                                const float* __restrict__ W2) {
    __shared__ float sU1t[Oq*49], sU2t[Oq*49];     // [o][t] pad 49
    __shared__ float sW1c[Oq*4], sW2c[Oq*4];       // [o][kk]
    int tid = threadIdx.x;
    int kbase = blockIdx.x * 4;
    for (int i = tid; i < Tq*Oq; i += 192) {
        int t = i >> 6, o = i & 63;
        sU1t[o*49 + t] = g_U1[i];
        sU2t[o*49 + t] = g_U2[i];
    }
    for (int i = tid; i < Oq*4; i += 192) {
        int o = i >> 2, k = i & 3;
        sW1c[i] = __ldg(&W1[o*WROW + kbase + k]);
        sW2c[i] = __ldg(&W2[o*WROW + kbase + k]);
    }
    __syncthreads();
    int t = tid % TP, kk = tid / TP;
    float acc = 0.f;
    if (t < Tq) {
        #pragma unroll 8
        for (int o = 0; o < Oq; o++)
            acc += sW1c[o*4 + kk] * sU2t[o*49 + t]
                 + sW2c[o*4 + kk] * sU1t[o*49 + t];
    }
    g_Vt[t*304 + kbase + kk] = acc;   // 0 for t>=45
}

// ---------------------------------------------------------------------------
// cp.async helper
// ---------------------------------------------------------------------------
__device__ __forceinline__ void cp16(float* sdst, const float* gsrc) {
    unsigned a = (unsigned)__cvta_generic_to_shared(sdst);
    asm volatile("cp.async.cg.shared.global [%0], [%1], 16;" :: "r"(a), "l"(gsrc));
}

// ---------------------------------------------------------------------------
// K1 (gemm): 128 blocks x 256 threads. 16 rows x 112 cols, K=300 (5x60).
//   f32x2 packed row-pair accumulation, double-buffered cp.async W staging.
//   Epilogue: score table (+e[t]), row max, exp -> g_E; ht -> g_ht.
// ---------------------------------------------------------------------------
__global__ void __launch_bounds__(256) gemm_kernel(
        const float* __restrict__ h,
        const float* __restrict__ Wg, const float* __restrict__ bg,
        const unsigned char* __restrict__ mask8) {
    extern __shared__ float sm[];
    float* sh2 = sm;                  // 8 pairs x 300 float2 = 4800 floats
    float* sW  = sm + 4800;           // 2 x NC*CST = 15232 floats
    float* ssv = sW;                  // epilogue alias: 16*48
    float* se  = sW + 16*TP;          // 48
    __shared__ int sp[5];
    __shared__ float swt[16];
    __shared__ float smx[16];

    int tid  = threadIdx.x;
    int row0 = blockIdx.x * 16;
    int b    = row0 >> 7;

    // ---- aspect span scan (dual bool-dtype robust) ----
    if (tid < 5) sp[tid] = (tid==0 || tid==3) ? Sq : ((tid==1 || tid==4) ? -1 : 0);
    __syncthreads();
    if (tid < 128 && mask8[(b<<7) + tid]) {
        atomicMin(&sp[0], tid); atomicMax(&sp[1], tid); atomicAdd(&sp[2], 1);
    }
    __syncthreads();
    bool valid8 = (sp[2] == 3 && sp[1] - sp[0] == 2);
    if (!valid8) {
        const int* m32 = (const int*)mask8;
        if (tid < 128 && m32[(b<<7) + tid] != 0) {
            atomicMin(&sp[3], tid); atomicMax(&sp[4], tid);
        }
    }
    __syncthreads();
    int st = valid8 ? sp[0] : sp[3];
    int en = valid8 ? sp[1] : sp[4];
    if (tid < 16) {
        int s = (row0 + tid) & 127;
        float w;
        if (s < st)      w = 1.0f - (float)(st - s) * (1.0f/128.0f);
        else if (s > en) w = 1.0f - (float)(s - en) * (1.0f/128.0f);
        else             w = 0.0f;
        swt[tid] = w;
    }
    __syncthreads();

    // ---- stage position-weighted h, packed as row pairs: sh2[(p*300+k)*2 + (r&1)] ----
    {
        const float4* h4 = (const float4*)(h + (size_t)row0 * Dq);
        for (int i = tid; i < 16*75; i += 256) {
            int r = i / 75, q = i - r*75;
            float4 v = h4[i];
            float w = swt[r];
            float* dst = sh2 + ((r >> 1)*300 + q*4)*2 + (r & 1);
            dst[0] = v.x*w; dst[2] = v.y*w; dst[4] = v.z*w; dst[6] = v.w*w;
        }
    }

    // cols: [Wg 0..63 | V 64..111], per chunk 112*15 float4
    #define STAGE_CHUNK(buf, cc)                                            \
        for (int i = tid; i < NC*15; i += 256) {                            \
            int col = i / 15, q = i - col*15;                               \
            const float* src = (col < 64)                                   \
                ? Wg   + (size_t)col      * Dq  + (cc)*KT + q*4             \
                : g_Vt + (size_t)(col-64) * 304 + (cc)*KT + q*4;            \
            cp16(&sW[(buf)*NC*CST + col*CST + q*4], src);                   \
        }                                                                   \
        asm volatile("cp.async.commit_group;" ::: "memory");

    STAGE_CHUNK(0, 0)

    // thread mapping: cg 0..63 | sg (0=ht col, 1=S col) | rh (row half)
    int cg = tid & 63;
    int sg = (tid >> 6) & 1;
    int rh = tid >> 7;
    // clamp keeps sg=1,cg>=48 threads inside the NC-column smem window
    // (their results are discarded in the epilogue).
    int wcol = sg ? (64 + (cg < TP ? cg : TP - 1)) : cg;
    unsigned long long acc[4] = {0ull, 0ull, 0ull, 0ull};
    const unsigned long long* sh2u = (const unsigned long long*)sh2;

    for (int c = 0; c < 5; c++) {
        if (c < 4) { STAGE_CHUNK((c+1)&1, c+1) }
        if (c < 4) asm volatile("cp.async.wait_group 1;" ::: "memory");
        else       asm volatile("cp.async.wait_group 0;" ::: "memory");
        __syncthreads();

        const float* wp = sW + (c & 1)*NC*CST + wcol*CST;
        #pragma unroll 3
        for (int k4 = 0; k4 < 15; k4++) {
            float4 wv = *(const float4*)&wp[k4*4];
            unsigned long long hk[4][4];
            #pragma unroll
            for (int j = 0; j < 4; j++) {
                // FIX: advance h with the K-chunk (+ c*KT) — was missing.
                const unsigned long long* hp =
                    &sh2u[(size_t)(rh*4 + j)*300 + c*KT + k4*4];
                ulonglong2 t0 = *(const ulonglong2*)(hp);
                ulonglong2 t1 = *(const ulonglong2*)(hp + 2);
                hk[j][0] = t0.x; hk[j][1] = t0.y; hk[j][2] = t1.x; hk[j][3] = t1.y;
            }
            #pragma unroll
            for (int kk = 0; kk < 4; kk++) {
                unsigned long long wpk;
                unsigned wu = __float_as_uint(((const float*)&wv)[kk]);
                asm("mov.b64 %0, {%1, %1};" : "=l"(wpk) : "r"(wu));
                #pragma unroll
                for (int j = 0; j < 4; j++)
                    asm("fma.rn.f32x2 %0, %1, %2, %0;"
                        : "+l"(acc[j]) : "l"(hk[j][kk]), "l"(wpk));
            }
        }
        __syncthreads();
    }

    // ---- epilogue ----
    if (sg == 0) {
        float bt = bg[cg];
        #pragma unroll
        for (int j = 0; j < 4; j++) {
            unsigned lo = (unsigned)(acc[j] & 0xffffffffu);
            unsigned hi = (unsigned)(acc[j] >> 32);
            int row = rh*8 + j*2;
            g_ht[(size_t)(row0 + row    )*Oq + cg] = __uint_as_float(lo) + bt;
            g_ht[(size_t)(row0 + row + 1)*Oq + cg] = __uint_as_float(hi) + bt;
        }
    } else if (cg < TP) {
        #pragma unroll
        for (int j = 0; j < 4; j++) {
            unsigned lo = (unsigned)(acc[j] & 0xffffffffu);
            unsigned hi = (unsigned)(acc[j] >> 32);
            int row = rh*8 + j*2;
            ssv[(row    )*TP + cg] = __uint_as_float(lo);
            ssv[(row + 1)*TP + cg] = __uint_as_float(hi);
        }
    }
    if (tid < TP) se[tid] = g_e[tid];
    __syncthreads();

    if (tid < 16) {
        float m = -1e30f;
        #pragma unroll 5
        for (int t = 0; t < Tq; t++) m = fmaxf(m, ssv[tid*TP + t] + se[t]);
        smx[tid] = m;
    }
    __syncthreads();
    for (int i = tid; i < 16*TP; i += 256) {
        int r = i / TP, t = i - r*TP;
        float v = (t > 0 && t < Tq) ? __expf((ssv[i] + se[t] - smx[r]) * 0.125f) : 0.f;
        g_E[(size_t)(row0 + r)*TP + t] = v;
    }
    #undef STAGE_CHUNK
}

// ---------------------------------------------------------------------------
// K2 (attn): 256 blocks x 256 threads, 8 rows/block. Gather e=sE[ty], row-sum,
//       out = relu((A @ h_trans)/(sum+1e-6) + bias). One warp per row.
// ---------------------------------------------------------------------------
__global__ void __launch_bounds__(256) attn_kernel(
        const int* __restrict__ dep,
        const float* __restrict__ bias,
        float* __restrict__ out) {
    __shared__ float sE[8*TP];
    __shared__ float sht[Sq*Oq];     // 32 KB
    __shared__ float sA[8*Sq];
    __shared__ float spart[8*4];
    __shared__ float sden[8];

    int tid = threadIdx.x;
    int gr0 = blockIdx.x * 8;
    int b   = gr0 >> 7;

    for (int i = tid; i < 8*TP; i += 256) sE[i] = g_E[(size_t)gr0*TP + i];
    {
        const float4* src = (const float4*)(g_ht + (size_t)b * Sq * Oq);
        float4* dst = (float4*)sht;
        for (int i = tid; i < Sq*Oq/4; i += 256) dst[i] = src[i];
    }
    __syncthreads();

    int pos = tid & 127, rhh = tid >> 7;
    int wid = tid >> 5, lane = tid & 31;
    #pragma unroll
    for (int rr = 0; rr < 4; rr++) {
        int row = rr*2 + rhh;
        int ty = dep[(size_t)(gr0 + row)*Sq + pos];
        float e = sE[row*TP + ty];
        sA[row*Sq + pos] = e;
        float s = e;
        #pragma unroll
        for (int off = 16; off; off >>= 1)
            s += __shfl_xor_sync(0xffffffffu, s, off);
        if (lane == 0) spart[row*4 + (wid & 3)] = s;
    }
    __syncthreads();
    if (tid < 8)
        sden[tid] = 1.0f / (spart[tid*4] + spart[tid*4+1] +
                            spart[tid*4+2] + spart[tid*4+3] + 1e-6f);
    __syncthreads();

    int o2 = tid & 31, g = tid >> 5;            // g = row (one warp per row)
    const float* Ar = sA + g*Sq;
    float ax = 0.f, ay = 0.f;
    #pragma unroll 8
    for (int u = 0; u < Sq; u += 4) {
        float4 av = *(const float4*)&Ar[u];
        float2 h0 = *(const float2*)&sht[(u+0)*Oq + o2*2];
        float2 h1 = *(const float2*)&sht[(u+1)*Oq + o2*2];
        float2 h2 = *(const float2*)&sht[(u+2)*Oq + o2*2];
        float2 h3 = *(const float2*)&sht[(u+3)*Oq + o2*2];
        ax += av.x*h0.x + av.y*h1.x + av.z*h2.x + av.w*h3.x;
        ay += av.x*h0.y + av.y*h1.y + av.z*h2.y + av.w*h3.y;
    }
    float den = sden[g];
    float2 bb = *(const float2*)&bias[o2*2];
    float ox = fmaxf(ax*den + bb.x, 0.f);
    float oy = fmaxf(ay*den + bb.y, 0.f);
    *(float2*)&out[(size_t)(gr0 + g)*Oq + o2*2] = make_float2(ox, oy);
}

// ---------------------------------------------------------------------------
// Inputs: h, dep_table, W1, b1, W2, b2, Wg, bg, bias, dep_type_matrix, aspect_mask
// ---------------------------------------------------------------------------
extern "C" void kernel_launch(void* const* d_in, const int* in_sizes, int n_in,
                              void* d_out, int out_size) {
    const float* h         = (const float*)d_in[0];
    const float* dep_table = (const float*)d_in[1];
    const float* W1        = (const float*)d_in[2];
    const float* b1        = (const float*)d_in[3];
    const float* W2        = (const float*)d_in[4];
    const float* b2        = (const float*)d_in[5];
    const float* Wg        = (const float*)d_in[6];
    const float* bg        = (const float*)d_in[7];
    const float* bias      = (const float*)d_in[8];
    const int*   dep       = (const int*)d_in[9];
    const unsigned char* mask = (const unsigned char*)d_in[10];

    const int gemm_smem = (4800 + 2*NC*CST) * (int)sizeof(float);   // 80128 B
    cudaFuncSetAttribute(gemm_kernel,
                         cudaFuncAttributeMaxDynamicSharedMemorySize, gemm_smem);

    u_kernel<<<Tq, 64>>>(dep_table, W1, b1, W2, b2);
    v_kernel<<<75, 192>>>(W1, W2);
    gemm_kernel<<<ROWS_TOT/16, 256, gemm_smem>>>(h, Wg, bg, mask);
    attn_kernel<<<ROWS_TOT/8, 256>>>(dep, bias, (float*)d_out);
}

// round 8
// speedup vs baseline: 1.8075x; 1.0666x over previous
#include <cuda_runtime.h>

#define Bq 16
#define Sq 128
#define Dq 300
#define Oq 64
#define Eq 16
#define Tq 45
#define TP 48               // padded type count
#define ROWS_TOT 2048
#define WROW 316
#define KT 60               // K-chunk
#define CST 68              // smem col stride (floats): 272B, 16B-aligned, 4-bank lane stride
#define WBUF (64*CST)       // per-buffer stride (max 64 cols)

// __device__ scratch (allocation-free rule)
__device__ float g_ht[ROWS_TOT*Oq];
__device__ float g_E [ROWS_TOT*TP];
__device__ float g_e [TP];          // zero-init covers t>=45
__device__ float g_Vt[TP*304];      // V transposed [t][k], rowlen 304

// ---------------------------------------------------------------------------
// cp.async helper
// ---------------------------------------------------------------------------
__device__ __forceinline__ void cp16(float* sdst, const float* gsrc) {
    unsigned a = (unsigned)__cvta_generic_to_shared(sdst);
    asm volatile("cp.async.cg.shared.global [%0], [%1], 16;" :: "r"(a), "l"(gsrc));
}

// ---------------------------------------------------------------------------
// K0 (prep): per-block smem recompute of U1/U2 from staged W tails + dep_table,
//   then V[t][kbase..kbase+3] -> g_Vt. Block 0 additionally emits e[t].
//   75 blocks x 192 threads.
// ---------------------------------------------------------------------------
__global__ void __launch_bounds__(192) prep_kernel(
        const float* __restrict__ dep_table,
        const float* __restrict__ W1, const float* __restrict__ b1,
        const float* __restrict__ W2, const float* __restrict__ b2) {
    __shared__ float sdt[Tq*Eq];                   // 720
    __shared__ float sWt1[Oq*Eq], sWt2[Oq*Eq];     // 1024 each
    __shared__ float sU1t[Oq*49], sU2t[Oq*49];     // [o][t] pad 49
    __shared__ float sW1c[Oq*4], sW2c[Oq*4];       // [o][kk]
    int tid = threadIdx.x;
    int kbase = blockIdx.x * 4;

    // stage W tails (coalesced float4) + dep_table + W k-columns
    for (int i = tid; i < Oq*4; i += 192) {        // 4 float4 per o-row
        int o = i >> 2, q = i & 3;
        *(float4*)&sWt1[o*Eq + q*4] = *(const float4*)&W1[o*WROW + Dq + q*4];
        *(float4*)&sWt2[o*Eq + q*4] = *(const float4*)&W2[o*WROW + Dq + q*4];
    }
    for (int i = tid; i < Tq*Eq/4; i += 192)
        *(float4*)&sdt[i*4] = *(const float4*)&dep_table[i*4];
    for (int i = tid; i < Oq*4; i += 192) {
        int o = i >> 2, k = i & 3;
        sW1c[i] = __ldg(&W1[o*WROW + kbase + k]);
        sW2c[i] = __ldg(&W2[o*WROW + kbase + k]);
    }
    __syncthreads();

    // U1/U2 from smem
    for (int i = tid; i < Tq*Oq; i += 192) {
        int t = i >> 6, o = i & 63;
        float s1 = 0.f, s2 = 0.f;
        #pragma unroll
        for (int e = 0; e < Eq; e++) {
            float de = sdt[t*Eq + e];
            s1 += sWt1[o*Eq + e] * de;
            s2 += sWt2[o*Eq + e] * de;
        }
        sU1t[o*49 + t] = s1;
        sU2t[o*49 + t] = s2;
    }
    __syncthreads();

    {
        int t = tid % TP, kk = tid / TP;
        float acc = 0.f;
        if (t < Tq) {
            #pragma unroll 8
            for (int o = 0; o < Oq; o++)
                acc += sW1c[o*4 + kk] * sU2t[o*49 + t]
                     + sW2c[o*4 + kk] * sU1t[o*49 + t];
        }
        g_Vt[t*304 + kbase + kk] = acc;            // 0 for t>=45
    }

    if (blockIdx.x == 0 && tid < Tq) {
        float e = 0.f;
        #pragma unroll 8
        for (int o = 0; o < Oq; o++) {
            float u1 = sU1t[o*49 + tid], u2 = sU2t[o*49 + tid];
            e += b1[o]*u2 + b2[o]*u1 + u1*u2;
        }
        g_e[tid] = e;
    }
}

// ---------------------------------------------------------------------------
// K1 (gemm): 256 blocks x 256 threads.
//   Type A (bx<128):  16 rows x 64 ht cols (Wg)       -> g_ht
//   Type B (bx>=128): 16 rows x 48 S cols (V) + softmax epilogue -> g_E
//   f32x2 packed row-pair accumulation, double-buffered cp.async staging.
// ---------------------------------------------------------------------------
__global__ void __launch_bounds__(256) gemm_kernel(
        const float* __restrict__ h,
        const float* __restrict__ Wg, const float* __restrict__ bg,
        const unsigned char* __restrict__ mask8) {
    extern __shared__ float sm[];
    float* sh2 = sm;                  // 8 pairs x 300 float2 = 4800 floats
    float* sW  = sm + 4800;           // 2 x WBUF = 8704 floats
    float* ssv = sW;                  // B epilogue alias: 16*48
    float* se  = sW + 16*TP;          // 48
    __shared__ int sp[5];
    __shared__ float swt[16];
    __shared__ float smx[16];

    int tid  = threadIdx.x;
    int bx   = blockIdx.x;
    bool tb  = bx >= 128;             // type B
    int row0 = (bx & 127) * 16;
    int b    = row0 >> 7;
    int ncols = tb ? TP : Oq;

    // ---- aspect span scan (dual bool-dtype robust) ----
    if (tid < 5) sp[tid] = (tid==0 || tid==3) ? Sq : ((tid==1 || tid==4) ? -1 : 0);
    __syncthreads();
    if (tid < 128 && mask8[(b<<7) + tid]) {
        atomicMin(&sp[0], tid); atomicMax(&sp[1], tid); atomicAdd(&sp[2], 1);
    }
    __syncthreads();
    bool valid8 = (sp[2] == 3 && sp[1] - sp[0] == 2);
    if (!valid8) {
        const int* m32 = (const int*)mask8;
        if (tid < 128 && m32[(b<<7) + tid] != 0) {
            atomicMin(&sp[3], tid); atomicMax(&sp[4], tid);
        }
    }
    __syncthreads();
    int st = valid8 ? sp[0] : sp[3];
    int en = valid8 ? sp[1] : sp[4];
    if (tid < 16) {
        int s = (row0 + tid) & 127;
        float w;
        if (s < st)      w = 1.0f - (float)(st - s) * (1.0f/128.0f);
        else if (s > en) w = 1.0f - (float)(s - en) * (1.0f/128.0f);
        else             w = 0.0f;
        swt[tid] = w;
    }
    __syncthreads();

    // ---- stage position-weighted h, packed row pairs: sh2[(p*300+k)*2 + (r&1)] ----
    {
        const float4* h4 = (const float4*)(h + (size_t)row0 * Dq);
        for (int i = tid; i < 16*75; i += 256) {
            int r = i / 75, q = i - r*75;
            float4 v = h4[i];
            float w = swt[r];
            float* dst = sh2 + ((r >> 1)*300 + q*4)*2 + (r & 1);
            dst[0] = v.x*w; dst[2] = v.y*w; dst[4] = v.z*w; dst[6] = v.w*w;
        }
    }

    #define STAGE_CHUNK(buf, cc)                                            \
        for (int i = tid; i < ncols*15; i += 256) {                         \
            int col = i / 15, q = i - col*15;                               \
            const float* src = tb                                           \
                ? g_Vt + (size_t)col * 304 + (cc)*KT + q*4                  \
                : Wg   + (size_t)col * Dq  + (cc)*KT + q*4;                 \
            cp16(&sW[(buf)*WBUF + col*CST + q*4], src);                     \
        }                                                                   \
        asm volatile("cp.async.commit_group;" ::: "memory");

    STAGE_CHUNK(0, 0)

    // thread mapping: cg 0..63 (col) | ph 0..3 (pairs ph*2, ph*2+1)
    int cg = tid & 63;
    int ph = tid >> 6;
    int wcol = (cg < ncols) ? cg : (ncols - 1);    // clamp inside staged window
    unsigned long long acc[2] = {0ull, 0ull};
    const unsigned long long* sh2u = (const unsigned long long*)sh2;

    for (int c = 0; c < 5; c++) {
        if (c < 4) { STAGE_CHUNK((c+1)&1, c+1) }
        if (c < 4) asm volatile("cp.async.wait_group 1;" ::: "memory");
        else       asm volatile("cp.async.wait_group 0;" ::: "memory");
        __syncthreads();

        const float* wp = sW + (c & 1)*WBUF + wcol*CST;
        #pragma unroll 5
        for (int k4 = 0; k4 < 15; k4++) {
            float4 wv = *(const float4*)&wp[k4*4];
            unsigned long long hk[2][4];
            #pragma unroll
            for (int j = 0; j < 2; j++) {
                const unsigned long long* hp =
                    &sh2u[(size_t)(ph*2 + j)*300 + c*KT + k4*4];
                ulonglong2 t0 = *(const ulonglong2*)(hp);
                ulonglong2 t1 = *(const ulonglong2*)(hp + 2);
                hk[j][0] = t0.x; hk[j][1] = t0.y; hk[j][2] = t1.x; hk[j][3] = t1.y;
            }
            #pragma unroll
            for (int kk = 0; kk < 4; kk++) {
                unsigned long long wpk;
                unsigned wu = __float_as_uint(((const float*)&wv)[kk]);
                asm("mov.b64 %0, {%1, %1};" : "=l"(wpk) : "r"(wu));
                #pragma unroll
                for (int j = 0; j < 2; j++)
                    asm("fma.rn.f32x2 %0, %1, %2, %0;"
                        : "+l"(acc[j]) : "l"(hk[j][kk]), "l"(wpk));
            }
        }
        __syncthreads();
    }

    // ---- epilogue ----
    if (!tb) {
        float bt = bg[cg];
        #pragma unroll
        for (int j = 0; j < 2; j++) {
            int r = (ph*2 + j)*2;
            unsigned lo = (unsigned)(acc[j] & 0xffffffffu);
            unsigned hi = (unsigned)(acc[j] >> 32);
            g_ht[(size_t)(row0 + r    )*Oq + cg] = __uint_as_float(lo) + bt;
            g_ht[(size_t)(row0 + r + 1)*Oq + cg] = __uint_as_float(hi) + bt;
        }
        return;
    }

    // type B: score table -> softmax numerators
    if (tid < TP) se[tid] = g_e[tid];
    if (cg < TP) {
        #pragma unroll
        for (int j = 0; j < 2; j++) {
            int r = (ph*2 + j)*2;
            unsigned lo = (unsigned)(acc[j] & 0xffffffffu);
            unsigned hi = (unsigned)(acc[j] >> 32);
            ssv[(r    )*TP + cg] = __uint_as_float(lo);
            ssv[(r + 1)*TP + cg] = __uint_as_float(hi);
        }
    }
    __syncthreads();
    if (tid < 16) {
        float m = -1e30f;
        #pragma unroll 5
        for (int t = 0; t < Tq; t++) m = fmaxf(m, ssv[tid*TP + t] + se[t]);
        smx[tid] = m;
    }
    __syncthreads();
    for (int i = tid; i < 16*TP; i += 256) {
        int r = i / TP, t = i - r*TP;
        float v = (t > 0 && t < Tq) ? __expf((ssv[i] + se[t] - smx[r]) * 0.125f) : 0.f;
        g_E[(size_t)(row0 + r)*TP + t] = v;
    }
    #undef STAGE_CHUNK
}

// ---------------------------------------------------------------------------
// K2 (attn): 512 blocks x 256 threads. Block = (8 rows, o-half of 32).
//   cp.async prefetch of the sht half overlaps the gather/row-sum phase.
// ---------------------------------------------------------------------------
__global__ void __launch_bounds__(256) attn_kernel(
        const int* __restrict__ dep,
        const float* __restrict__ bias,
        float* __restrict__ out) {
    __shared__ float sE[8*TP];
    __shared__ float sht[Sq*32];     // 16 KB: this block's o-half of h_trans
    __shared__ float sA[8*Sq];
    __shared__ float spart[8*4];
    __shared__ float sden[8];

    int tid = threadIdx.x;
    int bx  = blockIdx.x;
    int rg  = bx >> 1, oh = bx & 1;
    int gr0 = rg * 8;
    int b   = gr0 >> 7;

    // prefetch h_trans half (128 rows x 32 floats)
    {
        const float* src = g_ht + ((size_t)b * Sq) * Oq + oh*32;
        for (int i = tid; i < Sq*8; i += 256) {      // 1024 float4
            int u = i >> 3, q = i & 7;
            cp16(&sht[u*32 + q*4], src + (size_t)u*Oq + q*4);
        }
        asm volatile("cp.async.commit_group;" ::: "memory");
    }

    for (int i = tid; i < 8*TP; i += 256) sE[i] = g_E[(size_t)gr0*TP + i];
    __syncthreads();

    int pos = tid & 127, rhh = tid >> 7;
    int wid = tid >> 5, lane = tid & 31;
    #pragma unroll
    for (int rr = 0; rr < 4; rr++) {
        int row = rr*2 + rhh;
        int ty = dep[(size_t)(gr0 + row)*Sq + pos];
        float e = sE[row*TP + ty];
        sA[row*Sq + pos] = e;
        float s = e;
        #pragma unroll
        for (int off = 16; off; off >>= 1)
            s += __shfl_xor_sync(0xffffffffu, s, off);
        if (lane == 0) spart[row*4 + (wid & 3)] = s;
    }
    __syncthreads();
    if (tid < 8)
        sden[tid] = 1.0f / (spart[tid*4] + spart[tid*4+1] +
                            spart[tid*4+2] + spart[tid*4+3] + 1e-6f);
    asm volatile("cp.async.wait_group 0;" ::: "memory");
    __syncthreads();

    // matmul: one warp per row, lane = o within half
    int g = tid >> 5;
    const float* Ar = sA + g*Sq;
    float a = 0.f;
    #pragma unroll 8
    for (int u4 = 0; u4 < 32; u4++) {
        float4 av = *(const float4*)&Ar[u4*4];
        a += av.x * sht[(u4*4+0)*32 + lane]
           + av.y * sht[(u4*4+1)*32 + lane]
           + av.z * sht[(u4*4+2)*32 + lane]
           + av.w * sht[(u4*4+3)*32 + lane];
    }
    float v = a * sden[g] + bias[oh*32 + lane];
    out[(size_t)(gr0 + g)*Oq + oh*32 + lane] = fmaxf(v, 0.f);
}

// ---------------------------------------------------------------------------
// Inputs: h, dep_table, W1, b1, W2, b2, Wg, bg, bias, dep_type_matrix, aspect_mask
// ---------------------------------------------------------------------------
extern "C" void kernel_launch(void* const* d_in, const int* in_sizes, int n_in,
                              void* d_out, int out_size) {
    const float* h         = (const float*)d_in[0];
    const float* dep_table = (const float*)d_in[1];
    const float* W1        = (const float*)d_in[2];
    const float* b1        = (const float*)d_in[3];
    const float* W2        = (const float*)d_in[4];
    const float* b2        = (const float*)d_in[5];
    const float* Wg        = (const float*)d_in[6];
    const float* bg        = (const float*)d_in[7];
    const float* bias      = (const float*)d_in[8];
    const int*   dep       = (const int*)d_in[9];
    const unsigned char* mask = (const unsigned char*)d_in[10];

    const int gemm_smem = (4800 + 2*WBUF) * (int)sizeof(float);   // 54016 B
    cudaFuncSetAttribute(gemm_kernel,
                         cudaFuncAttributeMaxDynamicSharedMemorySize, gemm_smem);

    prep_kernel<<<75, 192>>>(dep_table, W1, b1, W2, b2);
    gemm_kernel<<<256, 256, gemm_smem>>>(h, Wg, bg, mask);
    attn_kernel<<<512, 256>>>(dep, bias, (float*)d_out);
}